// round 4
// baseline (speedup 1.0000x reference)
#include <cuda_runtime.h>
#include <cuda_bf16.h>
#include <math.h>

#define U_DIM 4096
#define T_DIM 200
#define K_DIM 64
#define Q_DIM 10000
#define H_DIM 128

// Scratch (device globals; no allocation in kernel_launch)
__device__ float2 d_tab[2 * Q_DIM];              // (mu, r) per (q, resp)
__device__ unsigned char d_kcq[Q_DIM];           // kc per question
__device__ float4 d_sc[T_DIM * U_DIM];           // (mu, r, ts, td) in (T,U) layout
__device__ unsigned char d_kcsc[T_DIM * U_DIM];  // kc in (T,U) layout

__device__ __forceinline__ float gelu_exact(float x) {
    return 0.5f * x * (1.0f + erff(x * 0.70710678118654752440f));
}

// ---------------------------------------------------------------------------
// Kernel A: per-(q,resp) MLP table + kc_of_q.
// kmap is a bool array up-converted by the harness to a 4-byte type
// (int32 or float32). Reading as int and testing !=0 is correct for BOTH:
// int32 true = 1, float32 true = 0x3F800000; false = 0 in both.
// ---------------------------------------------------------------------------
__global__ void mlp_table_kernel(
    const float* __restrict__ dmu, const float* __restrict__ smu,
    const int* __restrict__ kmap,
    const float* __restrict__ W1, const float* __restrict__ b1,
    const float* __restrict__ W2, const float* __restrict__ b2,
    const float* __restrict__ W3, const float* __restrict__ b3)
{
    // kc_of_q: grid-stride over questions (one-hot argmax == first set index)
    for (int q = blockIdx.x * blockDim.x + threadIdx.x; q < Q_DIM;
         q += gridDim.x * blockDim.x) {
        int kc = 0;
        #pragma unroll 8
        for (int k = K_DIM - 1; k >= 0; k--) {
            if (kmap[q * K_DIM + k] != 0) kc = k;
        }
        d_kcq[q] = (unsigned char)kc;
    }

    __shared__ float sh[4][H_DIM];
    const int wid = threadIdx.x >> 5;
    const int lane = threadIdx.x & 31;
    const int gw = blockIdx.x * 4 + wid;
    const int nw = gridDim.x * 4;

    for (int task = gw; task < 2 * Q_DIM; task += nw) {
        const int q = task >> 1;
        const float x2 = (float)(task & 1);
        const float x0 = dmu[q];
        const float x1 = smu[q];

        // layer 1: each lane owns 4 hidden units
        float h[4];
        #pragma unroll
        for (int j = 0; j < 4; j++) {
            int u = lane + j * 32;
            float a = fmaf(x0, W1[u],
                      fmaf(x1, W1[H_DIM + u],
                      fmaf(x2, W1[2 * H_DIM + u], b1[u])));
            h[j] = gelu_exact(a);
        }
        __syncwarp();
        #pragma unroll
        for (int j = 0; j < 4; j++) sh[wid][lane + j * 32] = h[j];
        __syncwarp();

        // layer 2: dense 128x128
        float acc[4];
        #pragma unroll
        for (int j = 0; j < 4; j++) acc[j] = b2[lane + j * 32];
        #pragma unroll 4
        for (int i = 0; i < H_DIM; i++) {
            float hv = sh[wid][i];
            #pragma unroll
            for (int j = 0; j < 4; j++)
                acc[j] = fmaf(hv, W2[i * H_DIM + lane + j * 32], acc[j]);
        }
        #pragma unroll
        for (int j = 0; j < 4; j++) h[j] = gelu_exact(acc[j]);
        __syncwarp();
        #pragma unroll
        for (int j = 0; j < 4; j++) sh[wid][lane + j * 32] = h[j];
        __syncwarp();

        // layer 3: 128 -> 2, warp reduce
        float o0 = 0.0f, o1 = 0.0f;
        #pragma unroll
        for (int j = 0; j < 4; j++) {
            int i = lane + j * 32;
            float hv = sh[wid][i];
            o0 = fmaf(hv, W3[2 * i], o0);
            o1 = fmaf(hv, W3[2 * i + 1], o1);
        }
        #pragma unroll
        for (int off = 16; off; off >>= 1) {
            o0 += __shfl_xor_sync(0xFFFFFFFFu, o0, off);
            o1 += __shfl_xor_sync(0xFFFFFFFFu, o1, off);
        }
        if (lane == 0) {
            float mu = gelu_exact(o0 + b3[0]);
            float lv = gelu_exact(o1 + b3[1]);
            float s = fmaxf(expf(0.5f * lv), 1e-8f);
            float inv = 1.0f / s;           // (STD_THETA/std)^2 with STD_THETA=1
            d_tab[task] = make_float2(mu, inv * inv);
        }
    }
}

// ---------------------------------------------------------------------------
// Kernel B: gather per-trial (mu, r, ts, td) + kc into transposed (T,U) scratch
// so the scan kernel reads fully coalesced.
// ---------------------------------------------------------------------------
__global__ void gather_kernel(
    const int* __restrict__ q_id, const int* __restrict__ resp,
    const float* __restrict__ dmu, const float* __restrict__ smu)
{
    int idx = blockIdx.x * blockDim.x + threadIdx.x;
    if (idx >= T_DIM * U_DIM) return;
    int t = idx / U_DIM;
    int u = idx - t * U_DIM;
    int q = q_id[u * T_DIM + t];
    int rs = resp[u * T_DIM + t];
    float2 mr = d_tab[2 * q + rs];
    float ts = smu[q];
    float td = dmu[q];
    d_sc[idx] = make_float4(mr.x, mr.y, ts, td);
    d_kcsc[idx] = d_kcq[q];
}

// ---------------------------------------------------------------------------
// Kernel C: per-user backward + forward scans.
// One warp (32 users) per block. KC state in shared, layout curr[k*32+lane]
// -> bank-conflict-free regardless of per-lane kc.
// ---------------------------------------------------------------------------
__global__ void __launch_bounds__(32, 1) scan_kernel(float* __restrict__ out)
{
    const int lane = threadIdx.x;
    const int u = blockIdx.x * 32 + lane;

    float barr[T_DIM];
    float carr[T_DIM];

    // backward Kalman recursion
    float b = 1.0f, c = 0.0f;
    #pragma unroll 4
    for (int t = T_DIM - 1; t >= 0; t--) {
        float4 f = d_sc[t * U_DIM + u];
        float bn = 1.0f / (1.0f + f.y + (1.0f - b));
        c = bn * (c + f.y * f.x);
        b = bn;
        barr[t] = b;
        carr[t] = c;
    }

    __shared__ float curr[K_DIM * 32];
    #pragma unroll
    for (int k = 0; k < K_DIM; k++) curr[k * 32 + lane] = 0.0f;
    __syncwarp();

    // forward scan with per-user KC state
    #pragma unroll 4
    for (int t = 0; t < T_DIM; t++) {
        int kc = d_kcsc[t * U_DIM + u];
        float prev = curr[kc * 32 + lane];
        float m = fmaf(barr[t], prev, carr[t]);
        curr[kc * 32 + lane] = m;
        float4 f = d_sc[t * U_DIM + u];
        out[u * T_DIM + t] = f.z * (m - f.w);   // ts * (ability - td)
    }

    // last_ability_kc: (U, K) appended after trial_logits
    float* o2 = out + (size_t)U_DIM * T_DIM + (size_t)u * K_DIM;
    #pragma unroll 4
    for (int k = 0; k < K_DIM; k++) o2[k] = curr[k * 32 + lane];
}

// ---------------------------------------------------------------------------
// Launch
// ---------------------------------------------------------------------------
extern "C" void kernel_launch(void* const* d_in, const int* in_sizes, int n_in,
                              void* d_out, int out_size)
{
    // metadata order: mask, q_id, kmap, resp, diff_mu, disc_mu, W1,b1,W2,b2,W3,b3
    const int* q_id = (const int*)d_in[1];
    const int* kmap = (const int*)d_in[2];
    const int* resp = (const int*)d_in[3];
    const float* dmu = (const float*)d_in[4];
    const float* smu = (const float*)d_in[5];
    const float* W1 = (const float*)d_in[6];
    const float* b1 = (const float*)d_in[7];
    const float* W2 = (const float*)d_in[8];
    const float* b2 = (const float*)d_in[9];
    const float* W3 = (const float*)d_in[10];
    const float* b3 = (const float*)d_in[11];
    float* out = (float*)d_out;

    mlp_table_kernel<<<256, 128>>>(dmu, smu, kmap, W1, b1, W2, b2, W3, b3);
    gather_kernel<<<(T_DIM * U_DIM + 255) / 256, 256>>>(q_id, resp, dmu, smu);
    scan_kernel<<<U_DIM / 32, 32>>>(out);
}

// round 5
// speedup vs baseline: 1.5625x; 1.5625x over previous
#include <cuda_runtime.h>
#include <cuda_bf16.h>
#include <math.h>

#define U_DIM 4096
#define T_DIM 200
#define K_DIM 64
#define Q_DIM 10000
#define H_DIM 128

// Scratch (device globals; no allocation in kernel_launch)
__device__ float2 d_tab[2 * Q_DIM];              // (mu, r) per (q, resp)
__device__ unsigned char d_kcq[Q_DIM];           // kc per question
__device__ float4 d_sc[T_DIM * U_DIM];           // (mu, r, ts, td) in (T,U) layout
__device__ unsigned char d_kcsc[T_DIM * U_DIM];  // kc in (T,U) layout

__device__ __forceinline__ float gelu_exact(float x) {
    return 0.5f * x * (1.0f + erff(x * 0.70710678118654752440f));
}

// ---------------------------------------------------------------------------
// Kernel A: per-(q,resp) MLP table + kc_of_q.
// One warp per 4 tasks (2 questions x resp {0,1}). Lane owns hidden units
// 4*lane..4*lane+3 (contiguous -> float4 weight loads). Layer-2 broadcasts
// h via __shfl_sync (unit i = element i&3 of lane i>>2); W2 read once per
// warp serves 4 accumulator sets -> 4x L1 traffic reduction.
// kmap arrives as int32-upconverted bool: test != 0.
// ---------------------------------------------------------------------------
__global__ void __launch_bounds__(256) mlp_table_kernel(
    const float* __restrict__ dmu, const float* __restrict__ smu,
    const int* __restrict__ kmap,
    const float* __restrict__ W1, const float* __restrict__ b1,
    const float* __restrict__ W2, const float* __restrict__ b2,
    const float* __restrict__ W3, const float* __restrict__ b3)
{
    // kc_of_q: grid-stride over questions (one-hot argmax == first set index)
    for (int q = blockIdx.x * blockDim.x + threadIdx.x; q < Q_DIM;
         q += gridDim.x * blockDim.x) {
        int kc = 0;
        #pragma unroll 8
        for (int k = K_DIM - 1; k >= 0; k--) {
            if (kmap[q * K_DIM + k] != 0) kc = k;
        }
        d_kcq[q] = (unsigned char)kc;
    }

    const int lane = threadIdx.x & 31;
    const int gw = (blockIdx.x * blockDim.x + threadIdx.x) >> 5;  // global warp
    if (gw >= Q_DIM / 2) return;
    const int q0 = gw * 2;

    const float x0a = dmu[q0],     x1a = smu[q0];
    const float x0b = dmu[q0 + 1], x1b = smu[q0 + 1];

    // ---- layer 1: units 4*lane+e ----
    const float4 w10 = *(const float4*)(W1 + 0 * H_DIM + 4 * lane);
    const float4 w11 = *(const float4*)(W1 + 1 * H_DIM + 4 * lane);
    const float4 w12 = *(const float4*)(W1 + 2 * H_DIM + 4 * lane);
    const float4 b1v = *(const float4*)(b1 + 4 * lane);
    float r0[4] = {w10.x, w10.y, w10.z, w10.w};
    float r1[4] = {w11.x, w11.y, w11.z, w11.w};
    float r2[4] = {w12.x, w12.y, w12.z, w12.w};
    float bb[4] = {b1v.x, b1v.y, b1v.z, b1v.w};

    // tasks: 0=(q0,resp0) 1=(q0,resp1) 2=(q0+1,resp0) 3=(q0+1,resp1)
    float h[4][4];
    #pragma unroll
    for (int e = 0; e < 4; e++) {
        float ba = fmaf(x0a, r0[e], fmaf(x1a, r1[e], bb[e]));
        float bbq = fmaf(x0b, r0[e], fmaf(x1b, r1[e], bb[e]));
        h[0][e] = gelu_exact(ba);
        h[1][e] = gelu_exact(ba + r2[e]);
        h[2][e] = gelu_exact(bbq);
        h[3][e] = gelu_exact(bbq + r2[e]);
    }

    // ---- layer 2: 128 x 128 dense, shfl broadcast, float4 W2 ----
    const float4 b2v = *(const float4*)(b2 + 4 * lane);
    float acc[4][4];
    #pragma unroll
    for (int t = 0; t < 4; t++) {
        acc[t][0] = b2v.x; acc[t][1] = b2v.y;
        acc[t][2] = b2v.z; acc[t][3] = b2v.w;
    }
    #pragma unroll 4
    for (int base = 0; base < 32; base++) {
        float4 w2r[4];
        #pragma unroll
        for (int ii = 0; ii < 4; ii++)
            w2r[ii] = *(const float4*)(W2 + (base * 4 + ii) * H_DIM + 4 * lane);
        #pragma unroll
        for (int t = 0; t < 4; t++) {
            #pragma unroll
            for (int ii = 0; ii < 4; ii++) {
                // input unit i = base*4+ii lives in lane (i>>2)=base, elem (i&3)=ii
                float hv = __shfl_sync(0xFFFFFFFFu, h[t][ii], base);
                acc[t][0] = fmaf(hv, w2r[ii].x, acc[t][0]);
                acc[t][1] = fmaf(hv, w2r[ii].y, acc[t][1]);
                acc[t][2] = fmaf(hv, w2r[ii].z, acc[t][2]);
                acc[t][3] = fmaf(hv, w2r[ii].w, acc[t][3]);
            }
        }
    }
    float h2[4][4];
    #pragma unroll
    for (int t = 0; t < 4; t++)
        #pragma unroll
        for (int e = 0; e < 4; e++)
            h2[t][e] = gelu_exact(acc[t][e]);

    // ---- layer 3: 128 -> 2, warp reduce ----
    const float4 w3a = *(const float4*)(W3 + 8 * lane);      // units 4l,4l+1
    const float4 w3b = *(const float4*)(W3 + 8 * lane + 4);  // units 4l+2,4l+3
    const float b30 = b3[0], b31 = b3[1];

    float o0[4], o1[4];
    #pragma unroll
    for (int t = 0; t < 4; t++) {
        o0[t] = fmaf(h2[t][0], w3a.x, fmaf(h2[t][1], w3a.z,
                fmaf(h2[t][2], w3b.x, h2[t][3] * w3b.z)));
        o1[t] = fmaf(h2[t][0], w3a.y, fmaf(h2[t][1], w3a.w,
                fmaf(h2[t][2], w3b.y, h2[t][3] * w3b.w)));
    }
    #pragma unroll
    for (int off = 16; off; off >>= 1) {
        #pragma unroll
        for (int t = 0; t < 4; t++) {
            o0[t] += __shfl_xor_sync(0xFFFFFFFFu, o0[t], off);
            o1[t] += __shfl_xor_sync(0xFFFFFFFFu, o1[t], off);
        }
    }
    if (lane == 0) {
        #pragma unroll
        for (int t = 0; t < 4; t++) {
            float mu = gelu_exact(o0[t] + b30);
            float lv = gelu_exact(o1[t] + b31);
            float s = fmaxf(expf(0.5f * lv), 1e-8f);
            float inv = 1.0f / s;           // (STD_THETA/std)^2, STD_THETA=1
            d_tab[4 * gw + t] = make_float2(mu, inv * inv);
        }
    }
}

// ---------------------------------------------------------------------------
// Kernel B: gather per-trial (mu, r, ts, td) + kc into transposed (T,U) scratch
// so the scan kernel reads fully coalesced.
// ---------------------------------------------------------------------------
__global__ void gather_kernel(
    const int* __restrict__ q_id, const int* __restrict__ resp,
    const float* __restrict__ dmu, const float* __restrict__ smu)
{
    int idx = blockIdx.x * blockDim.x + threadIdx.x;
    if (idx >= T_DIM * U_DIM) return;
    int t = idx / U_DIM;
    int u = idx - t * U_DIM;
    int q = q_id[u * T_DIM + t];
    int rs = resp[u * T_DIM + t];
    float2 mr = d_tab[2 * q + rs];
    float ts = smu[q];
    float td = dmu[q];
    d_sc[idx] = make_float4(mr.x, mr.y, ts, td);
    d_kcsc[idx] = d_kcq[q];
}

// ---------------------------------------------------------------------------
// Kernel C: per-user backward + forward scans.
// One warp (32 users) per block. KC state in shared, layout curr[k*32+lane]
// -> bank-conflict-free regardless of per-lane kc.
// ---------------------------------------------------------------------------
__global__ void __launch_bounds__(32, 1) scan_kernel(float* __restrict__ out)
{
    const int lane = threadIdx.x;
    const int u = blockIdx.x * 32 + lane;

    float barr[T_DIM];
    float carr[T_DIM];

    // backward Kalman recursion
    float b = 1.0f, c = 0.0f;
    #pragma unroll 4
    for (int t = T_DIM - 1; t >= 0; t--) {
        float4 f = d_sc[t * U_DIM + u];
        float bn = 1.0f / (1.0f + f.y + (1.0f - b));
        c = bn * (c + f.y * f.x);
        b = bn;
        barr[t] = b;
        carr[t] = c;
    }

    __shared__ float curr[K_DIM * 32];
    #pragma unroll
    for (int k = 0; k < K_DIM; k++) curr[k * 32 + lane] = 0.0f;
    __syncwarp();

    // forward scan with per-user KC state
    #pragma unroll 4
    for (int t = 0; t < T_DIM; t++) {
        int kc = d_kcsc[t * U_DIM + u];
        float prev = curr[kc * 32 + lane];
        float m = fmaf(barr[t], prev, carr[t]);
        curr[kc * 32 + lane] = m;
        float4 f = d_sc[t * U_DIM + u];
        out[u * T_DIM + t] = f.z * (m - f.w);   // ts * (ability - td)
    }

    // last_ability_kc: (U, K) appended after trial_logits
    float* o2 = out + (size_t)U_DIM * T_DIM + (size_t)u * K_DIM;
    #pragma unroll 4
    for (int k = 0; k < K_DIM; k++) o2[k] = curr[k * 32 + lane];
}

// ---------------------------------------------------------------------------
// Launch
// ---------------------------------------------------------------------------
extern "C" void kernel_launch(void* const* d_in, const int* in_sizes, int n_in,
                              void* d_out, int out_size)
{
    // metadata order: mask, q_id, kmap, resp, diff_mu, disc_mu, W1,b1,W2,b2,W3,b3
    const int* q_id = (const int*)d_in[1];
    const int* kmap = (const int*)d_in[2];
    const int* resp = (const int*)d_in[3];
    const float* dmu = (const float*)d_in[4];
    const float* smu = (const float*)d_in[5];
    const float* W1 = (const float*)d_in[6];
    const float* b1 = (const float*)d_in[7];
    const float* W2 = (const float*)d_in[8];
    const float* b2 = (const float*)d_in[9];
    const float* W3 = (const float*)d_in[10];
    const float* b3 = (const float*)d_in[11];
    float* out = (float*)d_out;

    // 5000 warps, one per 2 questions (4 (q,resp) tasks) -> 625 blocks of 256
    mlp_table_kernel<<<625, 256>>>(dmu, smu, kmap, W1, b1, W2, b2, W3, b3);
    gather_kernel<<<(T_DIM * U_DIM + 255) / 256, 256>>>(q_id, resp, dmu, smu);
    scan_kernel<<<U_DIM / 32, 32>>>(out);
}